// round 2
// baseline (speedup 1.0000x reference)
#include <cuda_runtime.h>
#include <math.h>

#define BATCH 16
#define SEQ   2048
#define DIM   512

// ---- scratch (static device globals; allocation-free per harness rules) ----
__device__ float g_Q[BATCH * SEQ * DIM];          // 64 MB
__device__ float g_K[BATCH * SEQ * DIM];          // 64 MB
__device__ float g_V[BATCH * SEQ * DIM];          // 64 MB
__device__ float g_S[(size_t)BATCH * SEQ * SEQ];  // 268 MB scores
__device__ float g_rowmax[BATCH * SEQ];
__device__ float g_rowinv[BATCH * SEQ];
__device__ float g_colsum[BATCH * SEQ];

// ============================================================================
// SGEMM NN: C[M,Nc] = A[M,K] * B[K,Nc]   (all row-major)
// 128x128 block tile, BK=8, 8x8 per-thread microtile, 256 threads
// ============================================================================
__global__ __launch_bounds__(256) void sgemm_nn(
    const float* __restrict__ A, const float* __restrict__ Bm,
    float* __restrict__ C, int M, int Nc, int K)
{
    __shared__ float As[8][128];
    __shared__ float Bs[8][128];

    const int tid  = threadIdx.x;
    const int crow = blockIdx.y * 128;
    const int ccol = blockIdx.x * 128;
    const int tx = tid & 15;        // 0..15
    const int ty = tid >> 4;        // 0..15
    const int arow = tid >> 1;            // 0..127
    const int acol = (tid & 1) * 4;       // 0 or 4
    const int brow = tid >> 5;            // 0..7
    const int bcol = (tid & 31) * 4;      // 0..124

    const float* Ab = A + (size_t)crow * K;
    const float* Bb = Bm + ccol;

    float acc[8][8] = {};

    for (int k0 = 0; k0 < K; k0 += 8) {
        float4 av = *(const float4*)(Ab + (size_t)arow * K + k0 + acol);
        As[acol + 0][arow] = av.x;
        As[acol + 1][arow] = av.y;
        As[acol + 2][arow] = av.z;
        As[acol + 3][arow] = av.w;
        float4 bv = *(const float4*)(Bb + (size_t)(k0 + brow) * Nc + bcol);
        *(float4*)(&Bs[brow][bcol]) = bv;
        __syncthreads();

        #pragma unroll
        for (int k = 0; k < 8; ++k) {
            float ra[8], rb[8];
            #pragma unroll
            for (int i = 0; i < 8; ++i) ra[i] = As[k][ty * 8 + i];
            #pragma unroll
            for (int j = 0; j < 8; ++j) rb[j] = Bs[k][tx * 8 + j];
            #pragma unroll
            for (int i = 0; i < 8; ++i)
                #pragma unroll
                for (int j = 0; j < 8; ++j)
                    acc[i][j] += ra[i] * rb[j];
        }
        __syncthreads();
    }

    #pragma unroll
    for (int i = 0; i < 8; ++i) {
        float* cp = C + (size_t)(crow + ty * 8 + i) * Nc + ccol + tx * 8;
        *(float4*)(cp)     = make_float4(acc[i][0], acc[i][1], acc[i][2], acc[i][3]);
        *(float4*)(cp + 4) = make_float4(acc[i][4], acc[i][5], acc[i][6], acc[i][7]);
    }
}

// ============================================================================
// Batched SGEMM NT: S[b][n][m] = scale * dot(Q[b][n][:], K[b][m][:])
// Q,K: [BATCH][SEQ][DIM] row-major. grid = (SEQ/128, SEQ/128, BATCH)
// ============================================================================
__global__ __launch_bounds__(256) void sgemm_nt_scores(
    const float* __restrict__ Q, const float* __restrict__ Kmat,
    float* __restrict__ S, float scale)
{
    __shared__ float As[8][128];
    __shared__ float Bs[8][128];

    const int b   = blockIdx.z;
    const int tid = threadIdx.x;
    const int tx  = tid & 15;
    const int ty  = tid >> 4;
    const int lrow = tid >> 1;        // 0..127
    const int lcol = (tid & 1) * 4;   // 0 or 4

    const float* Ab = Q    + (size_t)b * SEQ * DIM + (size_t)blockIdx.y * 128 * DIM;
    const float* Bb = Kmat + (size_t)b * SEQ * DIM + (size_t)blockIdx.x * 128 * DIM;
    float* Sb = S + (size_t)b * SEQ * SEQ;

    float acc[8][8] = {};

    for (int k0 = 0; k0 < DIM; k0 += 8) {
        float4 av = *(const float4*)(Ab + (size_t)lrow * DIM + k0 + lcol);
        As[lcol + 0][lrow] = av.x;
        As[lcol + 1][lrow] = av.y;
        As[lcol + 2][lrow] = av.z;
        As[lcol + 3][lrow] = av.w;
        float4 bv = *(const float4*)(Bb + (size_t)lrow * DIM + k0 + lcol);
        Bs[lcol + 0][lrow] = bv.x;
        Bs[lcol + 1][lrow] = bv.y;
        Bs[lcol + 2][lrow] = bv.z;
        Bs[lcol + 3][lrow] = bv.w;
        __syncthreads();

        #pragma unroll
        for (int k = 0; k < 8; ++k) {
            float ra[8], rb[8];
            #pragma unroll
            for (int i = 0; i < 8; ++i) ra[i] = As[k][ty * 8 + i];
            #pragma unroll
            for (int j = 0; j < 8; ++j) rb[j] = Bs[k][tx * 8 + j];
            #pragma unroll
            for (int i = 0; i < 8; ++i)
                #pragma unroll
                for (int j = 0; j < 8; ++j)
                    acc[i][j] += ra[i] * rb[j];
        }
        __syncthreads();
    }

    const int row0 = blockIdx.y * 128 + ty * 8;
    const int col0 = blockIdx.x * 128 + tx * 8;
    #pragma unroll
    for (int i = 0; i < 8; ++i) {
        float* sp = Sb + (size_t)(row0 + i) * SEQ + col0;
        *(float4*)(sp)     = make_float4(acc[i][0] * scale, acc[i][1] * scale,
                                         acc[i][2] * scale, acc[i][3] * scale);
        *(float4*)(sp + 4) = make_float4(acc[i][4] * scale, acc[i][5] * scale,
                                         acc[i][6] * scale, acc[i][7] * scale);
    }
}

// ============================================================================
// Per-row softmax stats: rowmax[r], rowinv[r] = 1/sum(exp(s - max))
// one block (256 thr) per row of SEQ=2048 elements
// ============================================================================
__global__ __launch_bounds__(256) void row_stats(
    const float* __restrict__ S, float* __restrict__ rowmax, float* __restrict__ rowinv)
{
    const int row = blockIdx.x;
    const float* r = S + (size_t)row * SEQ;
    const int t = threadIdx.x;

    float v[8];
    float m = -INFINITY;
    #pragma unroll
    for (int i = 0; i < 8; ++i) {
        v[i] = r[t + i * 256];
        m = fmaxf(m, v[i]);
    }

    __shared__ float red[256];
    red[t] = m;
    __syncthreads();
    for (int s = 128; s > 0; s >>= 1) {
        if (t < s) red[t] = fmaxf(red[t], red[t + s]);
        __syncthreads();
    }
    m = red[0];
    __syncthreads();

    float sum = 0.f;
    #pragma unroll
    for (int i = 0; i < 8; ++i) sum += __expf(v[i] - m);
    red[t] = sum;
    __syncthreads();
    for (int s = 128; s > 0; s >>= 1) {
        if (t < s) red[t] += red[t + s];
        __syncthreads();
    }
    if (t == 0) {
        rowmax[row] = m;
        rowinv[row] = 1.0f / red[0];
    }
}

// ============================================================================
// zero colsum + d_out (d_out is poisoned each replay)
// ============================================================================
__global__ void zero_kernel(float* __restrict__ colsum, float* __restrict__ out)
{
    int i = blockIdx.x * blockDim.x + threadIdx.x;
    if (i < BATCH * SEQ) colsum[i] = 0.f;
    if (i < BATCH * DIM) out[i] = 0.f;
}

// ============================================================================
// colsum[b][m] += sum_n exp(S[b][n][m] - rowmax[b][n]) * rowinv[b][n]
// grid = (SEQ/256, SEQ/128, BATCH), 256 threads (thread = one m column)
// ============================================================================
__global__ __launch_bounds__(256) void col_sum(
    const float* __restrict__ S, const float* __restrict__ rowmax,
    const float* __restrict__ rowinv, float* __restrict__ colsum)
{
    const int b  = blockIdx.z;
    const int m  = blockIdx.x * 256 + threadIdx.x;
    const int n0 = blockIdx.y * 128;
    const float* Sb = S + (size_t)b * SEQ * SEQ;
    const float* rm = rowmax + b * SEQ;
    const float* ri = rowinv + b * SEQ;

    float acc = 0.f;
    #pragma unroll 4
    for (int n = n0; n < n0 + 128; ++n) {
        acc += __expf(Sb[(size_t)n * SEQ + m] - rm[n]) * ri[n];
    }
    atomicAdd(&colsum[b * SEQ + m], acc);
}

// ============================================================================
// out[b][d] += (1/SEQ) * sum_m colsum[b][m] * V[b][m][d]
// grid = (BATCH, SEQ/256), 512 threads (thread = one d)
// ============================================================================
__global__ __launch_bounds__(512) void final_out(
    const float* __restrict__ V, const float* __restrict__ colsum,
    float* __restrict__ out)
{
    const int b  = blockIdx.x;
    const int m0 = blockIdx.y * 256;
    const int d  = threadIdx.x;
    const float* Vb = V + (size_t)b * SEQ * DIM;
    const float* cb = colsum + b * SEQ;

    float acc = 0.f;
    #pragma unroll 4
    for (int m = m0; m < m0 + 256; ++m) {
        acc += cb[m] * Vb[(size_t)m * DIM + d];
    }
    atomicAdd(&out[b * DIM + d], acc * (1.0f / SEQ));
}

// ============================================================================
extern "C" void kernel_launch(void* const* d_in, const int* in_sizes, int n_in,
                              void* d_out, int out_size)
{
    const float* x  = (const float*)d_in[0];
    const float* Wk = (const float*)d_in[1];
    const float* Wq = (const float*)d_in[2];
    const float* Wv = (const float*)d_in[3];
    float* out = (float*)d_out;

    float *Q, *K, *V, *S, *RM, *RI, *CS;
    cudaGetSymbolAddress((void**)&Q,  g_Q);
    cudaGetSymbolAddress((void**)&K,  g_K);
    cudaGetSymbolAddress((void**)&V,  g_V);
    cudaGetSymbolAddress((void**)&S,  g_S);
    cudaGetSymbolAddress((void**)&RM, g_rowmax);
    cudaGetSymbolAddress((void**)&RI, g_rowinv);
    cudaGetSymbolAddress((void**)&CS, g_colsum);

    // 1. projections: [B*SEQ, DIM] x [DIM, DIM]
    dim3 gp(DIM / 128, (BATCH * SEQ) / 128, 1);   // (4, 256)
    sgemm_nn<<<gp, 256>>>(x, Wq, Q, BATCH * SEQ, DIM, DIM);
    sgemm_nn<<<gp, 256>>>(x, Wk, K, BATCH * SEQ, DIM, DIM);
    sgemm_nn<<<gp, 256>>>(x, Wv, V, BATCH * SEQ, DIM, DIM);

    // 2. scores = Q K^T / sqrt(DIM), batched
    dim3 gs(SEQ / 128, SEQ / 128, BATCH);          // (16, 16, 16)
    const float scale = 1.0f / sqrtf((float)DIM);
    sgemm_nt_scores<<<gs, 256>>>(Q, K, S, scale);

    // 3. per-row softmax stats
    row_stats<<<BATCH * SEQ, 256>>>(S, RM, RI);

    // 4. zero accumulators (d_out is poisoned before each timed replay)
    zero_kernel<<<(BATCH * SEQ + 255) / 256, 256>>>(CS, out);

    // 5. softmax column sums
    dim3 gc(SEQ / 256, SEQ / 128, BATCH);          // (8, 16, 16)
    col_sum<<<gc, 256>>>(S, RM, RI, CS);

    // 6. out = (colsum/N) @ V
    dim3 gf(BATCH, SEQ / 256);                     // (16, 8)
    final_out<<<gf, 512>>>(V, CS, out);
}

// round 3
// speedup vs baseline: 2.4466x; 2.4466x over previous
#include <cuda_runtime.h>
#include <math.h>

#define BATCH 16
#define SEQ   2048
#define DIM   512

// ---- scratch (static device globals; allocation-free per harness rules) ----
__device__ float g_Q[BATCH * SEQ * DIM];          // 64 MB
__device__ float g_K[BATCH * SEQ * DIM];          // 64 MB
__device__ float g_V[BATCH * SEQ * DIM];          // 64 MB
__device__ float g_S[(size_t)BATCH * SEQ * SEQ];  // 268 MB scores
__device__ float g_rowmax[BATCH * SEQ];
__device__ float g_rowinv[BATCH * SEQ];
__device__ float g_colsum[BATCH * SEQ];

// ---- tf32 helpers ----------------------------------------------------------
__device__ __forceinline__ unsigned f2t(float f) {
    unsigned u;
    asm("cvt.rna.tf32.f32 %0, %1;" : "=r"(u) : "f"(f));
    return u;
}

__device__ __forceinline__ void mma8(float c[4], const unsigned a[4],
                                     unsigned b0, unsigned b1) {
    asm volatile(
        "mma.sync.aligned.m16n8k8.row.col.f32.tf32.tf32.f32 "
        "{%0,%1,%2,%3}, {%4,%5,%6,%7}, {%8,%9}, {%0,%1,%2,%3};"
        : "+f"(c[0]), "+f"(c[1]), "+f"(c[2]), "+f"(c[3])
        : "r"(a[0]), "r"(a[1]), "r"(a[2]), "r"(a[3]), "r"(b0), "r"(b1));
}

// Padded smem strides (words). SA=20: row offsets mod 32 cover all banks for
// A-fragment loads. SB=136: bank = 8*(lane%4)+lane/4 -> conflict-free B frags.
#define SA 20
#define SB 136

// ============================================================================
// TF32 tensor-core GEMM NN: C[M,N] = A[M,K] * B[K,N]  (row-major)
// 128x128 block, BK=16, 8 warps, warp tile 64x32 (4x4 m16n8k8 per k-step)
// ============================================================================
__global__ __launch_bounds__(256, 2) void tgemm_nn(
    const float* __restrict__ A, const float* __restrict__ Bm,
    float* __restrict__ C, int M, int N, int K)
{
    __shared__ unsigned As[128 * SA];
    __shared__ unsigned Bs[16 * SB];

    const int tid  = threadIdx.x;
    const int lane = tid & 31;
    const int warp = tid >> 5;
    const int wrow = (warp >> 2) * 64;   // 0 or 64
    const int wcol = (warp & 3) * 32;    // 0,32,64,96
    const int crow = blockIdx.y * 128;
    const int ccol = blockIdx.x * 128;

    const int ar = tid >> 1;             // 0..127
    const int ac = (tid & 1) * 8;        // 0 or 8
    const int br = tid >> 4;             // 0..15
    const int bc = (tid & 15) * 8;       // 0..120

    float c[4][4][4] = {};

    for (int k0 = 0; k0 < K; k0 += 16) {
        float4 v0 = *(const float4*)(A + (size_t)(crow + ar) * K + k0 + ac);
        float4 v1 = *(const float4*)(A + (size_t)(crow + ar) * K + k0 + ac + 4);
        unsigned* ap = &As[ar * SA + ac];
        ap[0] = f2t(v0.x); ap[1] = f2t(v0.y); ap[2] = f2t(v0.z); ap[3] = f2t(v0.w);
        ap[4] = f2t(v1.x); ap[5] = f2t(v1.y); ap[6] = f2t(v1.z); ap[7] = f2t(v1.w);

        float4 w0 = *(const float4*)(Bm + (size_t)(k0 + br) * N + ccol + bc);
        float4 w1 = *(const float4*)(Bm + (size_t)(k0 + br) * N + ccol + bc + 4);
        unsigned* bp = &Bs[br * SB + bc];
        bp[0] = f2t(w0.x); bp[1] = f2t(w0.y); bp[2] = f2t(w0.z); bp[3] = f2t(w0.w);
        bp[4] = f2t(w1.x); bp[5] = f2t(w1.y); bp[6] = f2t(w1.z); bp[7] = f2t(w1.w);
        __syncthreads();

        #pragma unroll
        for (int ks = 0; ks < 2; ++ks) {
            const int kk = ks * 8 + (lane & 3);
            unsigned a[4][4];
            #pragma unroll
            for (int mt = 0; mt < 4; ++mt) {
                const int r = wrow + mt * 16 + (lane >> 2);
                a[mt][0] = As[r * SA + kk];
                a[mt][1] = As[(r + 8) * SA + kk];
                a[mt][2] = As[r * SA + kk + 4];
                a[mt][3] = As[(r + 8) * SA + kk + 4];
            }
            #pragma unroll
            for (int nt = 0; nt < 4; ++nt) {
                const int cc = wcol + nt * 8 + (lane >> 2);
                unsigned b0 = Bs[kk * SB + cc];
                unsigned b1 = Bs[(kk + 4) * SB + cc];
                #pragma unroll
                for (int mt = 0; mt < 4; ++mt) mma8(c[mt][nt], a[mt], b0, b1);
            }
        }
        __syncthreads();
    }

    const int r0 = crow + wrow + (lane >> 2);
    const int c0 = ccol + wcol + (lane & 3) * 2;
    #pragma unroll
    for (int mt = 0; mt < 4; ++mt) {
        #pragma unroll
        for (int nt = 0; nt < 4; ++nt) {
            *(float2*)(C + (size_t)(r0 + mt * 16) * N + c0 + nt * 8) =
                make_float2(c[mt][nt][0], c[mt][nt][1]);
            *(float2*)(C + (size_t)(r0 + mt * 16 + 8) * N + c0 + nt * 8) =
                make_float2(c[mt][nt][2], c[mt][nt][3]);
        }
    }
}

// ============================================================================
// TF32 batched GEMM NT: S[b][n][m] = scale * dot(Q[b][n][:], K[b][m][:])
// grid = (SEQ/128, SEQ/128, BATCH)
// ============================================================================
__global__ __launch_bounds__(256, 2) void tgemm_nt_scores(
    const float* __restrict__ Q, const float* __restrict__ Kmat,
    float* __restrict__ S, float scale)
{
    __shared__ unsigned As[128 * SA];
    __shared__ unsigned Ks[128 * SA];

    const int b    = blockIdx.z;
    const int tid  = threadIdx.x;
    const int lane = tid & 31;
    const int warp = tid >> 5;
    const int wrow = (warp >> 2) * 64;
    const int wcol = (warp & 3) * 32;
    const int crow = blockIdx.y * 128;   // q rows
    const int ccol = blockIdx.x * 128;   // k rows (score cols)

    const int ar = tid >> 1;
    const int ac = (tid & 1) * 8;

    const float* Qb = Q    + (size_t)b * SEQ * DIM;
    const float* Kb = Kmat + (size_t)b * SEQ * DIM;
    float* Sb = S + (size_t)b * SEQ * SEQ;

    float c[4][4][4] = {};

    for (int k0 = 0; k0 < DIM; k0 += 16) {
        float4 v0 = *(const float4*)(Qb + (size_t)(crow + ar) * DIM + k0 + ac);
        float4 v1 = *(const float4*)(Qb + (size_t)(crow + ar) * DIM + k0 + ac + 4);
        unsigned* ap = &As[ar * SA + ac];
        ap[0] = f2t(v0.x); ap[1] = f2t(v0.y); ap[2] = f2t(v0.z); ap[3] = f2t(v0.w);
        ap[4] = f2t(v1.x); ap[5] = f2t(v1.y); ap[6] = f2t(v1.z); ap[7] = f2t(v1.w);

        float4 w0 = *(const float4*)(Kb + (size_t)(ccol + ar) * DIM + k0 + ac);
        float4 w1 = *(const float4*)(Kb + (size_t)(ccol + ar) * DIM + k0 + ac + 4);
        unsigned* kp = &Ks[ar * SA + ac];
        kp[0] = f2t(w0.x); kp[1] = f2t(w0.y); kp[2] = f2t(w0.z); kp[3] = f2t(w0.w);
        kp[4] = f2t(w1.x); kp[5] = f2t(w1.y); kp[6] = f2t(w1.z); kp[7] = f2t(w1.w);
        __syncthreads();

        #pragma unroll
        for (int ks = 0; ks < 2; ++ks) {
            const int kk = ks * 8 + (lane & 3);
            unsigned a[4][4];
            #pragma unroll
            for (int mt = 0; mt < 4; ++mt) {
                const int r = wrow + mt * 16 + (lane >> 2);
                a[mt][0] = As[r * SA + kk];
                a[mt][1] = As[(r + 8) * SA + kk];
                a[mt][2] = As[r * SA + kk + 4];
                a[mt][3] = As[(r + 8) * SA + kk + 4];
            }
            #pragma unroll
            for (int nt = 0; nt < 4; ++nt) {
                const int cc = wcol + nt * 8 + (lane >> 2);
                unsigned b0 = Ks[cc * SA + kk];
                unsigned b1 = Ks[cc * SA + kk + 4];
                #pragma unroll
                for (int mt = 0; mt < 4; ++mt) mma8(c[mt][nt], a[mt], b0, b1);
            }
        }
        __syncthreads();
    }

    const int r0 = crow + wrow + (lane >> 2);
    const int c0 = ccol + wcol + (lane & 3) * 2;
    #pragma unroll
    for (int mt = 0; mt < 4; ++mt) {
        #pragma unroll
        for (int nt = 0; nt < 4; ++nt) {
            *(float2*)(Sb + (size_t)(r0 + mt * 16) * SEQ + c0 + nt * 8) =
                make_float2(c[mt][nt][0] * scale, c[mt][nt][1] * scale);
            *(float2*)(Sb + (size_t)(r0 + mt * 16 + 8) * SEQ + c0 + nt * 8) =
                make_float2(c[mt][nt][2] * scale, c[mt][nt][3] * scale);
        }
    }
}

// ============================================================================
// Per-row softmax stats: rowmax[r], rowinv[r] = 1/sum(exp(s - max))
// ============================================================================
__global__ __launch_bounds__(256) void row_stats(
    const float* __restrict__ S, float* __restrict__ rowmax, float* __restrict__ rowinv)
{
    const int row = blockIdx.x;
    const float* r = S + (size_t)row * SEQ;
    const int t = threadIdx.x;

    float v[8];
    float m = -INFINITY;
    #pragma unroll
    for (int i = 0; i < 8; ++i) {
        v[i] = r[t + i * 256];
        m = fmaxf(m, v[i]);
    }

    __shared__ float red[256];
    red[t] = m;
    __syncthreads();
    for (int s = 128; s > 0; s >>= 1) {
        if (t < s) red[t] = fmaxf(red[t], red[t + s]);
        __syncthreads();
    }
    m = red[0];
    __syncthreads();

    float sum = 0.f;
    #pragma unroll
    for (int i = 0; i < 8; ++i) sum += __expf(v[i] - m);
    red[t] = sum;
    __syncthreads();
    for (int s = 128; s > 0; s >>= 1) {
        if (t < s) red[t] += red[t + s];
        __syncthreads();
    }
    if (t == 0) {
        rowmax[row] = m;
        rowinv[row] = 1.0f / red[0];
    }
}

__global__ void zero_kernel(float* __restrict__ colsum, float* __restrict__ out)
{
    int i = blockIdx.x * blockDim.x + threadIdx.x;
    if (i < BATCH * SEQ) colsum[i] = 0.f;
    if (i < BATCH * DIM) out[i] = 0.f;
}

// ============================================================================
// colsum[b][m] += sum_n exp(S[b][n][m] - rowmax[b][n]) * rowinv[b][n]
// ============================================================================
__global__ __launch_bounds__(256) void col_sum(
    const float* __restrict__ S, const float* __restrict__ rowmax,
    const float* __restrict__ rowinv, float* __restrict__ colsum)
{
    const int b  = blockIdx.z;
    const int m  = blockIdx.x * 256 + threadIdx.x;
    const int n0 = blockIdx.y * 128;
    const float* Sb = S + (size_t)b * SEQ * SEQ;
    const float* rm = rowmax + b * SEQ;
    const float* ri = rowinv + b * SEQ;

    float acc = 0.f;
    #pragma unroll 4
    for (int n = n0; n < n0 + 128; ++n) {
        acc += __expf(Sb[(size_t)n * SEQ + m] - rm[n]) * ri[n];
    }
    atomicAdd(&colsum[b * SEQ + m], acc);
}

// ============================================================================
// out[b][d] += (1/SEQ) * sum_m colsum[b][m] * V[b][m][d]
// ============================================================================
__global__ __launch_bounds__(512) void final_out(
    const float* __restrict__ V, const float* __restrict__ colsum,
    float* __restrict__ out)
{
    const int b  = blockIdx.x;
    const int m0 = blockIdx.y * 256;
    const int d  = threadIdx.x;
    const float* Vb = V + (size_t)b * SEQ * DIM;
    const float* cb = colsum + b * SEQ;

    float acc = 0.f;
    #pragma unroll 4
    for (int m = m0; m < m0 + 256; ++m) {
        acc += cb[m] * Vb[(size_t)m * DIM + d];
    }
    atomicAdd(&out[b * DIM + d], acc * (1.0f / SEQ));
}

// ============================================================================
extern "C" void kernel_launch(void* const* d_in, const int* in_sizes, int n_in,
                              void* d_out, int out_size)
{
    const float* x  = (const float*)d_in[0];
    const float* Wk = (const float*)d_in[1];
    const float* Wq = (const float*)d_in[2];
    const float* Wv = (const float*)d_in[3];
    float* out = (float*)d_out;

    float *Q, *K, *V, *S, *RM, *RI, *CS;
    cudaGetSymbolAddress((void**)&Q,  g_Q);
    cudaGetSymbolAddress((void**)&K,  g_K);
    cudaGetSymbolAddress((void**)&V,  g_V);
    cudaGetSymbolAddress((void**)&S,  g_S);
    cudaGetSymbolAddress((void**)&RM, g_rowmax);
    cudaGetSymbolAddress((void**)&RI, g_rowinv);
    cudaGetSymbolAddress((void**)&CS, g_colsum);

    // 1. projections: [B*SEQ, DIM] x [DIM, DIM]  (tf32 tensor cores)
    dim3 gp(DIM / 128, (BATCH * SEQ) / 128, 1);   // (4, 256)
    tgemm_nn<<<gp, 256>>>(x, Wq, Q, BATCH * SEQ, DIM, DIM);
    tgemm_nn<<<gp, 256>>>(x, Wk, K, BATCH * SEQ, DIM, DIM);
    tgemm_nn<<<gp, 256>>>(x, Wv, V, BATCH * SEQ, DIM, DIM);

    // 2. scores = Q K^T / sqrt(DIM), batched (tf32 tensor cores)
    dim3 gs(SEQ / 128, SEQ / 128, BATCH);          // (16, 16, 16)
    const float scale = 1.0f / sqrtf((float)DIM);
    tgemm_nt_scores<<<gs, 256>>>(Q, K, S, scale);

    // 3. per-row softmax stats
    row_stats<<<BATCH * SEQ, 256>>>(S, RM, RI);

    // 4. zero accumulators (d_out is poisoned before each timed replay)
    zero_kernel<<<(BATCH * SEQ + 255) / 256, 256>>>(CS, out);

    // 5. softmax column sums
    dim3 gc(SEQ / 256, SEQ / 128, BATCH);          // (8, 16, 16)
    col_sum<<<gc, 256>>>(S, RM, RI, CS);

    // 6. out = (colsum/N) @ V
    dim3 gf(BATCH, SEQ / 256);                     // (16, 8)
    final_out<<<gf, 512>>>(V, CS, out);
}